// round 2
// baseline (speedup 1.0000x reference)
#include <cuda_runtime.h>
#include <cuda_bf16.h>

#define T_SEQ 2048
#define NBATCH 16
#define DM 1024
#define HH 512

// ---------------- device scratch (sanctioned: __device__ globals) ----------------
__device__ float g_X[(size_t)T_SEQ * NBATCH * DM];          // embedded inputs [t*16+b][1024]
__device__ float g_XpF[(size_t)T_SEQ * NBATCH * 2048];      // fwd gate preacts, permuted
__device__ float g_XpB[(size_t)T_SEQ * NBATCH * 2048];      // bwd gate preacts, permuted
__device__ float g_H0f[(size_t)T_SEQ * NBATCH * HH];        // layer0 fwd hidden [t*16+b][512]
__device__ float g_H0b[(size_t)T_SEQ * NBATCH * HH];        // layer0 bwd hidden
__device__ float g_h[2][2][NBATCH * HH];                    // [dir][parity][b*512+u]
__device__ unsigned g_cnt[2];                               // per-direction barrier counters

// ---------------- helpers ----------------
__device__ __forceinline__ float to_tf32(float x) {
    unsigned u;
    asm("cvt.rna.tf32.f32 %0, %1;" : "=r"(u) : "f"(x));
    return __uint_as_float(u);
}
__device__ __forceinline__ unsigned FB(float x) { return __float_as_uint(x); }

__device__ __forceinline__ void mma8(float c[4], const unsigned a[4], const unsigned b[2]) {
    asm volatile(
        "mma.sync.aligned.m16n8k8.row.col.f32.tf32.tf32.f32 "
        "{%0,%1,%2,%3},{%4,%5,%6,%7},{%8,%9},{%0,%1,%2,%3};"
        : "+f"(c[0]), "+f"(c[1]), "+f"(c[2]), "+f"(c[3])
        : "r"(a[0]), "r"(a[1]), "r"(a[2]), "r"(a[3]), "r"(b[0]), "r"(b[1]));
}

__device__ __forceinline__ float sigm(float x) { return 1.f / (1.f + __expf(-x)); }
__device__ __forceinline__ float tanh_(float x) {
    float xc = fminf(fmaxf(x, -20.f), 20.f);
    float e = __expf(-2.f * xc);
    return (1.f - e) / (1.f + e);
}

// ---------------- embedding gather ----------------
__global__ void __launch_bounds__(256) embed_kernel(
    const int* __restrict__ ids, const float* __restrict__ tab, float* __restrict__ X) {
    int i = blockIdx.x * 256 + threadIdx.x;     // over T*B*256 float4s
    int q = i & 255, row = i >> 8;
    int b = row & 15, t = row >> 4;
    int id = ids[b * T_SEQ + t];
    reinterpret_cast<float4*>(X)[(size_t)row * 256 + q] =
        reinterpret_cast<const float4*>(tab)[(size_t)id * 256 + q];
}

// ---------------- TF32 GEMM: Xp[perm] = A[M,K] @ W[K,2048] + bias ----------------
// Block tile 128x64, BK=16, 8 warps (4M x 2N), warp tile 32x32.
// Epilogue writes the permuted scan layout:
//   addr = (((t*32 + blk)*64) + gate*16 + j) * 16 + b
// where t=row>>4, b=row&15, gate=col>>9, u=col&511, blk=u>>4, j=u&15.
__global__ void __launch_bounds__(256) gemm_kernel(
    const float* __restrict__ A, const float* __restrict__ W,
    const float* __restrict__ bias, float* __restrict__ C, int K) {
    __shared__ __align__(16) float As[128][20];
    __shared__ __align__(16) float Bs[16][72];
    const int tid = threadIdx.x, lane = tid & 31, warp = tid >> 5;
    const int wm = warp & 3, wn = warp >> 2;
    const int gid = lane >> 2, tig = lane & 3;
    const int r0 = blockIdx.x * 128, n0 = blockIdx.y * 64;
    float acc[2][4][4] = {};
    const int arow = tid >> 2, akq = (tid & 3) * 4;
    const int brow = tid >> 4, bnq = (tid & 15) * 4;

    for (int k0 = 0; k0 < K; k0 += 16) {
        float4 v0 = *(const float4*)(A + (size_t)(r0 + arow) * K + k0 + akq);
        float4 v1 = *(const float4*)(A + (size_t)(r0 + arow + 64) * K + k0 + akq);
        float4 w0 = *(const float4*)(W + (size_t)(k0 + brow) * 2048 + n0 + bnq);
        As[arow][akq + 0] = to_tf32(v0.x); As[arow][akq + 1] = to_tf32(v0.y);
        As[arow][akq + 2] = to_tf32(v0.z); As[arow][akq + 3] = to_tf32(v0.w);
        As[arow + 64][akq + 0] = to_tf32(v1.x); As[arow + 64][akq + 1] = to_tf32(v1.y);
        As[arow + 64][akq + 2] = to_tf32(v1.z); As[arow + 64][akq + 3] = to_tf32(v1.w);
        Bs[brow][bnq + 0] = to_tf32(w0.x); Bs[brow][bnq + 1] = to_tf32(w0.y);
        Bs[brow][bnq + 2] = to_tf32(w0.z); Bs[brow][bnq + 3] = to_tf32(w0.w);
        __syncthreads();
#pragma unroll
        for (int kk = 0; kk < 16; kk += 8) {
            unsigned a[2][4], bb[4][2];
            const int mb = wm * 32;
            a[0][0] = FB(As[mb + gid][kk + tig]);      a[0][1] = FB(As[mb + gid + 8][kk + tig]);
            a[0][2] = FB(As[mb + gid][kk + tig + 4]);  a[0][3] = FB(As[mb + gid + 8][kk + tig + 4]);
            a[1][0] = FB(As[mb + 16 + gid][kk + tig]); a[1][1] = FB(As[mb + 24 + gid][kk + tig]);
            a[1][2] = FB(As[mb + 16 + gid][kk + tig + 4]); a[1][3] = FB(As[mb + 24 + gid][kk + tig + 4]);
#pragma unroll
            for (int nt = 0; nt < 4; ++nt) {
                int nb = wn * 32 + nt * 8 + gid;
                bb[nt][0] = FB(Bs[kk + tig][nb]);
                bb[nt][1] = FB(Bs[kk + tig + 4][nb]);
            }
#pragma unroll
            for (int mt = 0; mt < 2; ++mt)
#pragma unroll
                for (int nt = 0; nt < 4; ++nt)
                    mma8(acc[mt][nt], a[mt], bb[nt]);
        }
        __syncthreads();
    }
#pragma unroll
    for (int mt = 0; mt < 2; ++mt) {
#pragma unroll
        for (int nt = 0; nt < 4; ++nt) {
#pragma unroll
            for (int e = 0; e < 4; ++e) {
                int row = r0 + wm * 32 + mt * 16 + gid + ((e >> 1) * 8);
                int col = n0 + wn * 32 + nt * 8 + 2 * tig + (e & 1);
                float v = acc[mt][nt][e] + bias[col];
                int t = row >> 4, b = row & 15;
                int gt = col >> 9, u = col & 511;
                size_t addr = (((size_t)t * 32 + (u >> 4)) * 64 + gt * 16 + (u & 15)) * 16 + b;
                C[addr] = v;
            }
        }
    }
}

// ---------------- zero barrier/state before each scan ----------------
__global__ void __launch_bounds__(256) zero_kernel() {
    int i = blockIdx.x * 256 + threadIdx.x;
    if (i < 2 * 2 * NBATCH * HH) ((float*)g_h)[i] = 0.f;
    if (i < 2) g_cnt[i] = 0u;
}

// ---------------- persistent LSTM scan (one layer, both directions) ----------------
// 64 blocks: [0,32)=fwd, [32,64)=bwd. Block owns 16 units -> 64 gate columns.
// gates^T (64 x 16) = Wslice^T (64x512) @ h^T (512x16), tf32 mma,
// 8 warps = 4 m-tiles x 2 k-halves, smem partial reduction.
#define SCAN_SMEM_FLOATS (32768 + 16 * 516 + 64 * 17)
#define SCAN_SMEM_BYTES (SCAN_SMEM_FLOATS * 4)

__global__ void __launch_bounds__(256, 1) scan_kernel(
    const float* __restrict__ WhF, const float* __restrict__ WhB,
    const float* __restrict__ XpF, const float* __restrict__ XpB,
    float* __restrict__ outF, float* __restrict__ outB, int mode) {
    extern __shared__ float sm[];
    float* WtF_ = sm;                    // [4 mt][64 kt][32 lane][4] = 32768 floats
    float* hs = sm + 32768;              // [16][516]
    float* Gb = hs + 16 * 516;           // [64][17]

    const int dir = blockIdx.x >> 5;
    const int blk = blockIdx.x & 31;
    const int u0 = blk * 16;
    const float* Wh = dir ? WhB : WhF;
    const float* Xp = dir ? XpB : XpF;
    float* out = dir ? outB : outF;

    const int tid = threadIdx.x, lane = tid & 31, warp = tid >> 5;
    const int mt = warp & 3, kh = warp >> 2;
    const int gid = lane >> 2, tig = lane & 3;

    // Load W_h slice into fragment-major smem (once).
    for (int idx = tid; idx < 32768; idx += 256) {
        int q = idx & 3;
        int ln = (idx >> 2) & 31;
        int kt = (idx >> 7) & 63;
        int mtt = idx >> 13;
        int lgid = ln >> 2, ltig = ln & 3;
        int m = mtt * 16 + lgid + (q & 1) * 8;
        int k = kt * 8 + ltig + (q >> 1) * 4;
        int gt = m >> 4, j = m & 15;
        sm[idx] = to_tf32(Wh[(size_t)k * 2048 + gt * 512 + u0 + j]);
    }
    __syncthreads();

    const int ej = tid & 15, eb = tid >> 4;   // unit-within-block, batch
    float c_state = 0.f;
    unsigned* bar = &g_cnt[dir];
    const float* Afbase = WtF_ + ((size_t)(mt * 64 + kh * 32) * 32 + lane) * 4;

    for (int s = 0; s < T_SEQ; ++s) {
        int t = dir ? (T_SEQ - 1 - s) : s;

        // prefetch this thread's input-gate preactivations (coalesced)
        const float* xp = Xp + ((size_t)t * 32 + blk) * 1024;
        float xi = xp[(0 * 16 + ej) * 16 + eb];
        float xg = xp[(1 * 16 + ej) * 16 + eb];
        float xf = xp[(2 * 16 + ej) * 16 + eb];
        float xo = xp[(3 * 16 + ej) * 16 + eb];

        // load h (16x512) from global into smem, tf32-rounded
        const float* hsrc = g_h[dir][s & 1];
#pragma unroll
        for (int i = 0; i < 8; ++i) {
            int f = tid + i * 256;            // 2048 float4s
            int b = f >> 7, q = f & 127;
            float4 v = reinterpret_cast<const float4*>(hsrc)[f];
            v.x = to_tf32(v.x); v.y = to_tf32(v.y); v.z = to_tf32(v.z); v.w = to_tf32(v.w);
            *reinterpret_cast<float4*>(hs + b * 516 + q * 4) = v;
        }
        __syncthreads();

        // recurrent GEMM
        float cacc0[4] = {}, cacc1[4] = {};
#pragma unroll 4
        for (int kt = 0; kt < 32; ++kt) {
            float4 av = *reinterpret_cast<const float4*>(Afbase + kt * 128);
            unsigned a[4] = {FB(av.x), FB(av.y), FB(av.z), FB(av.w)};
            int k0 = (kh * 32 + kt) * 8;
            unsigned b0[2], b1[2];
            b0[0] = FB(hs[gid * 516 + k0 + tig]);
            b0[1] = FB(hs[gid * 516 + k0 + tig + 4]);
            b1[0] = FB(hs[(8 + gid) * 516 + k0 + tig]);
            b1[1] = FB(hs[(8 + gid) * 516 + k0 + tig + 4]);
            mma8(cacc0, a, b0);
            mma8(cacc1, a, b1);
        }

        // reduce the two k-halves through smem
        int rb = mt * 16 + gid;
        if (kh == 0) {
            Gb[rb * 17 + 2 * tig] = cacc0[0];
            Gb[rb * 17 + 2 * tig + 1] = cacc0[1];
            Gb[(rb + 8) * 17 + 2 * tig] = cacc0[2];
            Gb[(rb + 8) * 17 + 2 * tig + 1] = cacc0[3];
            Gb[rb * 17 + 8 + 2 * tig] = cacc1[0];
            Gb[rb * 17 + 8 + 2 * tig + 1] = cacc1[1];
            Gb[(rb + 8) * 17 + 8 + 2 * tig] = cacc1[2];
            Gb[(rb + 8) * 17 + 8 + 2 * tig + 1] = cacc1[3];
        }
        __syncthreads();
        if (kh == 1) {
            Gb[rb * 17 + 2 * tig] += cacc0[0];
            Gb[rb * 17 + 2 * tig + 1] += cacc0[1];
            Gb[(rb + 8) * 17 + 2 * tig] += cacc0[2];
            Gb[(rb + 8) * 17 + 2 * tig + 1] += cacc0[3];
            Gb[rb * 17 + 8 + 2 * tig] += cacc1[0];
            Gb[rb * 17 + 8 + 2 * tig + 1] += cacc1[1];
            Gb[(rb + 8) * 17 + 8 + 2 * tig] += cacc1[2];
            Gb[(rb + 8) * 17 + 8 + 2 * tig + 1] += cacc1[3];
        }
        __syncthreads();

        // elementwise LSTM update: thread handles (unit ej, batch eb)
        float gi = Gb[(0 * 16 + ej) * 17 + eb] + xi;
        float gg = Gb[(1 * 16 + ej) * 17 + eb] + xg;
        float gf = Gb[(2 * 16 + ej) * 17 + eb] + xf;
        float go = Gb[(3 * 16 + ej) * 17 + eb] + xo;
        float fgate = sigm(gf + 1.0f);
        c_state = fgate * c_state + sigm(gi) * tanh_(gg);
        float h = sigm(go) * tanh_(c_state);

        g_h[dir][(s + 1) & 1][eb * 512 + u0 + ej] = h;
        if (mode == 0)
            out[((size_t)t * 16 + eb) * 512 + u0 + ej] = h;
        else
            out[((size_t)eb * 2048 + t) * 1024 + dir * 512 + u0 + ej] = h;

        // inter-block barrier (per direction)
        __threadfence();
        __syncthreads();
        if (tid == 0) {
            atomicAdd(bar, 1u);
            unsigned tgt = 32u * (unsigned)(s + 1);
            volatile unsigned* p = bar;
            while (*p < tgt) {}
        }
        __syncthreads();
        __threadfence();
    }
}

// ---------------- launch ----------------
extern "C" void kernel_launch(void* const* d_in, const int* in_sizes, int n_in,
                              void* d_out, int out_size) {
    const int* ids = (const int*)d_in[0];
    const float* tab = (const float*)d_in[1];
    const float* fW0 = (const float*)d_in[2];
    const float* fb0 = (const float*)d_in[3];
    const float* fW1 = (const float*)d_in[4];
    const float* fb1 = (const float*)d_in[5];
    const float* bW0 = (const float*)d_in[6];
    const float* bb0 = (const float*)d_in[7];
    const float* bW1 = (const float*)d_in[8];
    const float* bb1 = (const float*)d_in[9];
    float* out = (float*)d_out;

    cudaFuncSetAttribute(scan_kernel, cudaFuncAttributeMaxDynamicSharedMemorySize,
                         SCAN_SMEM_BYTES);

    float *X, *XpF, *XpB, *H0f, *H0b;
    cudaGetSymbolAddress((void**)&X, g_X);
    cudaGetSymbolAddress((void**)&XpF, g_XpF);
    cudaGetSymbolAddress((void**)&XpB, g_XpB);
    cudaGetSymbolAddress((void**)&H0f, g_H0f);
    cudaGetSymbolAddress((void**)&H0b, g_H0b);

    embed_kernel<<<(T_SEQ * NBATCH * 256) / 256, 256>>>(ids, tab, X);

    dim3 gg(256, 32);
    gemm_kernel<<<gg, 256>>>(X, fW0, fb0, XpF, 1024);
    gemm_kernel<<<gg, 256>>>(X, bW0, bb0, XpB, 1024);
    zero_kernel<<<128, 256>>>();
    scan_kernel<<<64, 256, SCAN_SMEM_BYTES>>>(fW0 + 1024 * 2048, bW0 + 1024 * 2048,
                                              XpF, XpB, H0f, H0b, 0);
    gemm_kernel<<<gg, 256>>>(H0f, fW1, fb1, XpF, 512);
    gemm_kernel<<<gg, 256>>>(H0b, bW1, bb1, XpB, 512);
    zero_kernel<<<128, 256>>>();
    scan_kernel<<<64, 256, SCAN_SMEM_BYTES>>>(fW1 + 512 * 2048, bW1 + 512 * 2048,
                                              XpF, XpB, out, out, 1);
}

// round 4
// speedup vs baseline: 1.0636x; 1.0636x over previous
#include <cuda_runtime.h>
#include <cuda_bf16.h>

#define T_SEQ 2048
#define NBATCH 16
#define DM 1024
#define HH 512

// ---------------- device scratch ----------------
__device__ float g_X[(size_t)T_SEQ * NBATCH * DM];
__device__ float g_XpF[(size_t)T_SEQ * NBATCH * 2048];
__device__ float g_XpB[(size_t)T_SEQ * NBATCH * 2048];
__device__ float g_H0f[(size_t)T_SEQ * NBATCH * HH];
__device__ float g_H0b[(size_t)T_SEQ * NBATCH * HH];
__device__ float g_h[2][2][NBATCH * HH];
__device__ unsigned g_cnt[2];

// ---------------- helpers ----------------
__device__ __forceinline__ float to_tf32(float x) {
    unsigned u;
    asm("cvt.rna.tf32.f32 %0, %1;" : "=r"(u) : "f"(x));
    return __uint_as_float(u);
}
__device__ __forceinline__ unsigned FT(float x) {   // fp32 -> tf32 bits (rna)
    unsigned u;
    asm("cvt.rna.tf32.f32 %0, %1;" : "=r"(u) : "f"(x));
    return u;
}
__device__ __forceinline__ unsigned FB(float x) { return __float_as_uint(x); }

__device__ __forceinline__ void mma8(float c[4], const unsigned a[4], const unsigned b[2]) {
    asm volatile(
        "mma.sync.aligned.m16n8k8.row.col.f32.tf32.tf32.f32 "
        "{%0,%1,%2,%3},{%4,%5,%6,%7},{%8,%9},{%0,%1,%2,%3};"
        : "+f"(c[0]), "+f"(c[1]), "+f"(c[2]), "+f"(c[3])
        : "r"(a[0]), "r"(a[1]), "r"(a[2]), "r"(a[3]), "r"(b[0]), "r"(b[1]));
}

__device__ __forceinline__ void cpasync16(void* s, const void* g) {
    unsigned ss = (unsigned)__cvta_generic_to_shared(s);
    asm volatile("cp.async.ca.shared.global [%0], [%1], 16;" :: "r"(ss), "l"(g));
}
__device__ __forceinline__ void cp_commit() { asm volatile("cp.async.commit_group;"); }
__device__ __forceinline__ void cp_wait2() { asm volatile("cp.async.wait_group 2;"); }

__device__ __forceinline__ float sigm(float x) { return 1.f / (1.f + __expf(-x)); }
__device__ __forceinline__ float tanh_(float x) {
    float xc = fminf(fmaxf(x, -20.f), 20.f);
    float e = __expf(-2.f * xc);
    return (1.f - e) / (1.f + e);
}

// ---------------- embedding gather ----------------
__global__ void __launch_bounds__(256) embed_kernel(
    const int* __restrict__ ids, const float* __restrict__ tab, float* __restrict__ X) {
    int i = blockIdx.x * 256 + threadIdx.x;
    int q = i & 255, row = i >> 8;
    int b = row & 15, t = row >> 4;
    int id = ids[b * T_SEQ + t];
    reinterpret_cast<float4*>(X)[(size_t)row * 256 + q] =
        reinterpret_cast<const float4*>(tab)[(size_t)id * 256 + q];
}

// ---------------- pipelined TF32 GEMM (dynamic smem) ----------------
// C[perm] = A[M,K] @ W[K,2048] + bias. Block tile 128x128, BK=16, 3-stage cp.async.
// 8 warps: 2 (m) x 4 (n), warp tile 64x32. tf32 cvt at fragment load.
// smem layout: As[3][128][20] then Bs[3][16][136]
#define GA_STRIDE 20
#define GB_STRIDE 136
#define GA_TILE (128 * GA_STRIDE)
#define GB_TILE (16 * GB_STRIDE)
#define GEMM_SMEM_FLOATS (3 * GA_TILE + 3 * GB_TILE)
#define GEMM_SMEM_BYTES (GEMM_SMEM_FLOATS * 4)

__global__ void __launch_bounds__(256) gemm_kernel(
    const float* __restrict__ A, const float* __restrict__ W,
    const float* __restrict__ bias, float* __restrict__ C, int K) {
    extern __shared__ __align__(16) float gsm[];
    float* As = gsm;                         // [3][128][20]
    float* Bs = gsm + 3 * GA_TILE;           // [3][16][136]
    const int tid = threadIdx.x, lane = tid & 31, warp = tid >> 5;
    const int wm = warp >> 2, wn = warp & 3;
    const int gid = lane >> 2, tig = lane & 3;
    const int r0 = blockIdx.x * 128, n0 = blockIdx.y * 128;
    float acc[4][4][4] = {};

    const int ntiles = K >> 4;
    const int ar0 = tid >> 2, aq0 = (tid & 3) * 4;
    const int ar1 = (tid + 256) >> 2, aq1 = ((tid + 256) & 3) * 4;
    const int br0 = tid >> 5, bq0 = (tid & 31) * 4;
    const int br1 = (tid + 256) >> 5, bq1 = ((tid + 256) & 31) * 4;

#define COPY_TILE(s, kt)                                                                     \
    do {                                                                                     \
        int k0_ = (kt) << 4;                                                                 \
        cpasync16(As + (s) * GA_TILE + ar0 * GA_STRIDE + aq0,                                \
                  A + (size_t)(r0 + ar0) * K + k0_ + aq0);                                   \
        cpasync16(As + (s) * GA_TILE + ar1 * GA_STRIDE + aq1,                                \
                  A + (size_t)(r0 + ar1) * K + k0_ + aq1);                                   \
        cpasync16(Bs + (s) * GB_TILE + br0 * GB_STRIDE + bq0,                                \
                  W + (size_t)(k0_ + br0) * 2048 + n0 + bq0);                                \
        cpasync16(Bs + (s) * GB_TILE + br1 * GB_STRIDE + bq1,                                \
                  W + (size_t)(k0_ + br1) * 2048 + n0 + bq1);                                \
    } while (0)

    COPY_TILE(0, 0); cp_commit();
    COPY_TILE(1, 1); cp_commit();
    COPY_TILE(2, 2); cp_commit();

    for (int t = 0; t < ntiles; ++t) {
        int s = t % 3;
        const float* Asb = As + s * GA_TILE;
        const float* Bsb = Bs + s * GB_TILE;
        cp_wait2();
        __syncthreads();
#pragma unroll
        for (int kk = 0; kk < 16; kk += 8) {
            unsigned a[4][4], bb[4][2];
#pragma unroll
            for (int mt = 0; mt < 4; ++mt) {
                int m = wm * 64 + mt * 16;
                a[mt][0] = FT(Asb[(m + gid) * GA_STRIDE + kk + tig]);
                a[mt][1] = FT(Asb[(m + gid + 8) * GA_STRIDE + kk + tig]);
                a[mt][2] = FT(Asb[(m + gid) * GA_STRIDE + kk + tig + 4]);
                a[mt][3] = FT(Asb[(m + gid + 8) * GA_STRIDE + kk + tig + 4]);
            }
#pragma unroll
            for (int nt = 0; nt < 4; ++nt) {
                int nb = wn * 32 + nt * 8 + gid;
                bb[nt][0] = FT(Bsb[(kk + tig) * GB_STRIDE + nb]);
                bb[nt][1] = FT(Bsb[(kk + tig + 4) * GB_STRIDE + nb]);
            }
#pragma unroll
            for (int mt = 0; mt < 4; ++mt)
#pragma unroll
                for (int nt = 0; nt < 4; ++nt)
                    mma8(acc[mt][nt], a[mt], bb[nt]);
        }
        __syncthreads();
        if (t + 3 < ntiles) COPY_TILE(s, t + 3);
        cp_commit();
    }
#undef COPY_TILE

#pragma unroll
    for (int mt = 0; mt < 4; ++mt) {
#pragma unroll
        for (int nt = 0; nt < 4; ++nt) {
#pragma unroll
            for (int e = 0; e < 4; ++e) {
                int row = r0 + wm * 64 + mt * 16 + gid + ((e >> 1) * 8);
                int col = n0 + wn * 32 + nt * 8 + 2 * tig + (e & 1);
                float v = acc[mt][nt][e] + bias[col];
                int tt = row >> 4, b = row & 15;
                int gt = col >> 9, u = col & 511;
                size_t addr = (((size_t)tt * 32 + (u >> 4)) * 64 + gt * 16 + (u & 15)) * 16 + b;
                C[addr] = v;
            }
        }
    }
}

// ---------------- zero barrier/state ----------------
__global__ void __launch_bounds__(256) zero_kernel() {
    int i = blockIdx.x * 256 + threadIdx.x;
    if (i < 2 * 2 * NBATCH * HH) ((float*)g_h)[i] = 0.f;
    if (i < 2) g_cnt[i] = 0u;
}

// ---------------- persistent LSTM scan ----------------
#define SCAN_SMEM_FLOATS (32768 + 16 * 516 + 2 * 64 * 17)
#define SCAN_SMEM_BYTES (SCAN_SMEM_FLOATS * 4)

__global__ void __launch_bounds__(256, 1) scan_kernel(
    const float* __restrict__ WhF, const float* __restrict__ WhB,
    const float* __restrict__ XpF, const float* __restrict__ XpB,
    float* __restrict__ outF, float* __restrict__ outB, int mode) {
    extern __shared__ float sm[];
    float* hs = sm + 32768;              // [16][516]
    float* Gb = hs + 16 * 516;           // [2][64][17]

    const int dir = blockIdx.x >> 5;
    const int blk = blockIdx.x & 31;
    const int u0 = blk * 16;
    const float* Wh = dir ? WhB : WhF;
    const float* Xp = dir ? XpB : XpF;
    float* out = dir ? outB : outF;

    const int tid = threadIdx.x, lane = tid & 31, warp = tid >> 5;
    const int mt = warp & 3, kh = warp >> 2;
    const int gid = lane >> 2, tig = lane & 3;

    // W_h slice -> fragment-major smem
    for (int idx = tid; idx < 32768; idx += 256) {
        int q = idx & 3;
        int ln = (idx >> 2) & 31;
        int kt = (idx >> 7) & 63;
        int mtt = idx >> 13;
        int lgid = ln >> 2, ltig = ln & 3;
        int m = mtt * 16 + lgid + (q & 1) * 8;
        int k = kt * 8 + ltig + (q >> 1) * 4;
        int gt = m >> 4, j = m & 15;
        sm[idx] = to_tf32(Wh[(size_t)k * 2048 + gt * 512 + u0 + j]);
    }
    __syncthreads();

    const int ej = tid & 15, eb = tid >> 4;
    float c_state = 0.f;
    unsigned* bar = &g_cnt[dir];
    const float* Afbase = sm + ((size_t)(mt * 64 + kh * 32) * 32 + lane) * 4;
    float* Gp = Gb + kh * 1088;

    for (int s = 0; s < T_SEQ; ++s) {
        int t = dir ? (T_SEQ - 1 - s) : s;

        const float* xp = Xp + ((size_t)t * 32 + blk) * 1024;
        float xi = xp[(0 * 16 + ej) * 16 + eb];
        float xg = xp[(1 * 16 + ej) * 16 + eb];
        float xf = xp[(2 * 16 + ej) * 16 + eb];
        float xo = xp[(3 * 16 + ej) * 16 + eb];

        const float* hsrc = g_h[dir][s & 1];
#pragma unroll
        for (int i = 0; i < 8; ++i) {
            int f = tid + i * 256;
            int b = f >> 7, q = f & 127;
            float4 v = reinterpret_cast<const float4*>(hsrc)[f];
            v.x = to_tf32(v.x); v.y = to_tf32(v.y); v.z = to_tf32(v.z); v.w = to_tf32(v.w);
            *reinterpret_cast<float4*>(hs + b * 516 + q * 4) = v;
        }
        __syncthreads();

        float cacc0[4] = {}, cacc1[4] = {};
#pragma unroll 4
        for (int kt = 0; kt < 32; ++kt) {
            float4 av = *reinterpret_cast<const float4*>(Afbase + kt * 128);
            unsigned a[4] = {FB(av.x), FB(av.y), FB(av.z), FB(av.w)};
            int k0 = (kh * 32 + kt) * 8;
            unsigned b0[2], b1[2];
            b0[0] = FB(hs[gid * 516 + k0 + tig]);
            b0[1] = FB(hs[gid * 516 + k0 + tig + 4]);
            b1[0] = FB(hs[(8 + gid) * 516 + k0 + tig]);
            b1[1] = FB(hs[(8 + gid) * 516 + k0 + tig + 4]);
            mma8(cacc0, a, b0);
            mma8(cacc1, a, b1);
        }

        // each k-half writes its own buffer; summed at read (single sync)
        int rb = mt * 16 + gid;
        Gp[rb * 17 + 2 * tig] = cacc0[0];
        Gp[rb * 17 + 2 * tig + 1] = cacc0[1];
        Gp[(rb + 8) * 17 + 2 * tig] = cacc0[2];
        Gp[(rb + 8) * 17 + 2 * tig + 1] = cacc0[3];
        Gp[rb * 17 + 8 + 2 * tig] = cacc1[0];
        Gp[rb * 17 + 8 + 2 * tig + 1] = cacc1[1];
        Gp[(rb + 8) * 17 + 8 + 2 * tig] = cacc1[2];
        Gp[(rb + 8) * 17 + 8 + 2 * tig + 1] = cacc1[3];
        __syncthreads();

        float gi = Gb[(0 * 16 + ej) * 17 + eb] + Gb[1088 + (0 * 16 + ej) * 17 + eb] + xi;
        float gg = Gb[(1 * 16 + ej) * 17 + eb] + Gb[1088 + (1 * 16 + ej) * 17 + eb] + xg;
        float gf = Gb[(2 * 16 + ej) * 17 + eb] + Gb[1088 + (2 * 16 + ej) * 17 + eb] + xf;
        float go = Gb[(3 * 16 + ej) * 17 + eb] + Gb[1088 + (3 * 16 + ej) * 17 + eb] + xo;
        float fgate = sigm(gf + 1.0f);
        c_state = fgate * c_state + sigm(gi) * tanh_(gg);
        float h = sigm(go) * tanh_(c_state);

        g_h[dir][(s + 1) & 1][eb * 512 + u0 + ej] = h;
        if (mode == 0)
            out[((size_t)t * 16 + eb) * 512 + u0 + ej] = h;
        else
            out[((size_t)eb * 2048 + t) * 1024 + dir * 512 + u0 + ej] = h;

        __threadfence();
        __syncthreads();
        if (tid == 0) {
            atomicAdd(bar, 1u);
            unsigned tgt = 32u * (unsigned)(s + 1);
            volatile unsigned* p = bar;
            while (*p < tgt) {}
        }
        __syncthreads();
        __threadfence();
    }
}

// ---------------- launch ----------------
extern "C" void kernel_launch(void* const* d_in, const int* in_sizes, int n_in,
                              void* d_out, int out_size) {
    const int* ids = (const int*)d_in[0];
    const float* tab = (const float*)d_in[1];
    const float* fW0 = (const float*)d_in[2];
    const float* fb0 = (const float*)d_in[3];
    const float* fW1 = (const float*)d_in[4];
    const float* fb1 = (const float*)d_in[5];
    const float* bW0 = (const float*)d_in[6];
    const float* bb0 = (const float*)d_in[7];
    const float* bW1 = (const float*)d_in[8];
    const float* bb1 = (const float*)d_in[9];
    float* out = (float*)d_out;

    cudaFuncSetAttribute(scan_kernel, cudaFuncAttributeMaxDynamicSharedMemorySize,
                         SCAN_SMEM_BYTES);
    cudaFuncSetAttribute(gemm_kernel, cudaFuncAttributeMaxDynamicSharedMemorySize,
                         GEMM_SMEM_BYTES);

    float *X, *XpF, *XpB, *H0f, *H0b;
    cudaGetSymbolAddress((void**)&X, g_X);
    cudaGetSymbolAddress((void**)&XpF, g_XpF);
    cudaGetSymbolAddress((void**)&XpB, g_XpB);
    cudaGetSymbolAddress((void**)&H0f, g_H0f);
    cudaGetSymbolAddress((void**)&H0b, g_H0b);

    embed_kernel<<<(T_SEQ * NBATCH * 256) / 256, 256>>>(ids, tab, X);

    dim3 gg(256, 16);
    gemm_kernel<<<gg, 256, GEMM_SMEM_BYTES>>>(X, fW0, fb0, XpF, 1024);
    gemm_kernel<<<gg, 256, GEMM_SMEM_BYTES>>>(X, bW0, bb0, XpB, 1024);
    zero_kernel<<<128, 256>>>();
    scan_kernel<<<64, 256, SCAN_SMEM_BYTES>>>(fW0 + 1024 * 2048, bW0 + 1024 * 2048,
                                              XpF, XpB, H0f, H0b, 0);
    gemm_kernel<<<gg, 256, GEMM_SMEM_BYTES>>>(H0f, fW1, fb1, XpF, 512);
    gemm_kernel<<<gg, 256, GEMM_SMEM_BYTES>>>(H0b, bW1, bb1, XpB, 512);
    zero_kernel<<<128, 256>>>();
    scan_kernel<<<64, 256, SCAN_SMEM_BYTES>>>(fW1 + 512 * 2048, bW1 + 512 * 2048,
                                              XpF, XpB, out, out, 1);
}